// round 14
// baseline (speedup 1.0000x reference)
// R13: B fragments loaded DIRECTLY from gmem (float2 -> cvt -> MMA), no B smem.
// Kills 24KB/iter of the measured 64KB/iter L1 traffic (the binding 68% pipe)
// and shortens the per-iter chain. B staged one k16-step ahead in 8 regs.
// A path unchanged from R12 (cp.async double-buffer + ldmatrix, 80B rows).
#include <cuda_runtime.h>
#include <cuda_bf16.h>
#include <cstdint>

#define T_TOK 1024
#define H_DIM 1024
#define NE 32
#define TOPK 4
#define F_DIM 1024
#define TWO_F 2048
#define LIMIT 7.0f
#define ALPHA 1.702f
#define EPS 1e-5f

#define BM 128
#define BN 128
#define BK 32
#define ROWE 40            // bf16 elems per A smem row (80B stride)
#define STG_E (128 * ROWE)
#define STG_B (STG_E * 2)

// ------------------- scratch -------------------
__device__ __nv_bfloat16 g_tnorm_h[T_TOK * H_DIM];
__device__ int   g_counts[NE];
__device__ int   g_bases[NE];
__device__ int   g_expert_ids[T_TOK * TOPK];
__device__ float g_weights[T_TOK * TOPK];
__device__ int   g_slot_token[T_TOK * TOPK];
__device__ float g_slot_weight[T_TOK * TOPK];
__device__ int   g_token_slot[T_TOK * TOPK];
__device__ __nv_bfloat16 g_act_h[(size_t)T_TOK * TOPK * F_DIM];
__device__ float g_y[(size_t)T_TOK * TOPK * H_DIM];

// ------------------- helpers -------------------
__device__ __forceinline__ void mma_bf16(float (&d)[4], const uint32_t (&a)[4],
                                         uint32_t b0, uint32_t b1) {
    asm volatile(
        "mma.sync.aligned.m16n8k16.row.col.f32.bf16.bf16.f32 "
        "{%0,%1,%2,%3}, {%4,%5,%6,%7}, {%8,%9}, {%0,%1,%2,%3};\n"
        : "+f"(d[0]), "+f"(d[1]), "+f"(d[2]), "+f"(d[3])
        : "r"(a[0]), "r"(a[1]), "r"(a[2]), "r"(a[3]), "r"(b0), "r"(b1));
}
__device__ __forceinline__ void ldsm4(uint32_t (&r)[4], uint32_t addr) {
    asm volatile("ldmatrix.sync.aligned.m8n8.x4.shared.b16 {%0,%1,%2,%3}, [%4];"
                 : "=r"(r[0]), "=r"(r[1]), "=r"(r[2]), "=r"(r[3]) : "r"(addr));
}
__device__ __forceinline__ uint32_t packbf(float lo, float hi) {
    uint32_t r;
    asm("cvt.rn.bf16x2.f32 %0, %1, %2;" : "=r"(r) : "f"(hi), "f"(lo));
    return r;
}
__device__ __forceinline__ void cp16(uint32_t dst, const void* src, uint32_t sz) {
    asm volatile("cp.async.ca.shared.global [%0], [%1], 16, %2;\n"
                 ::"r"(dst), "l"(src), "r"(sz));
}
__device__ __forceinline__ void cp_commit() { asm volatile("cp.async.commit_group;\n"); }
__device__ __forceinline__ void cp_wait0() { asm volatile("cp.async.wait_group 0;\n"); }

// load one k16-step of B fragments for 4 col-blocks (8 packed bf16x2 regs)
__device__ __forceinline__ void ldB(const float* p0, const float* p1,
                                    const float* p2, const float* p3,
                                    int off, uint32_t (&v)[8]) {
    const float* p[4] = {p0, p1, p2, p3};
#pragma unroll
    for (int ni = 0; ni < 4; ni++) {
        float2 x0 = *(const float2*)(p[ni] + off);
        float2 x1 = *(const float2*)(p[ni] + off + 8);
        v[2 * ni + 0] = packbf(x0.x, x0.y);
        v[2 * ni + 1] = packbf(x1.x, x1.y);
    }
}

// ------------------- kernel 0 -------------------
__global__ void k_zero() {
    if (threadIdx.x < NE) g_counts[threadIdx.x] = 0;
}

// ------------------- kernel 1: rmsnorm + gate + top4 + softmax ----------------
__global__ void k_gate(const float* __restrict__ x, const float* __restrict__ scale,
                       const float* __restrict__ gw, const float* __restrict__ gb) {
    int t = blockIdx.x;
    int tid = threadIdx.x;
    __shared__ float sh[H_DIM];
    __shared__ float red[8];
    __shared__ float logits[NE];
    const float* xr = x + (size_t)t * H_DIM;

    float ss = 0.f;
    for (int i = tid; i < H_DIM; i += 256) { float v = xr[i]; ss += v * v; }
    for (int o = 16; o; o >>= 1) ss += __shfl_xor_sync(~0u, ss, o);
    int warp = tid >> 5, lane = tid & 31;
    if (!lane) red[warp] = ss;
    __syncthreads();
    if (tid < 8) {
        float s = red[tid];
        for (int o = 4; o; o >>= 1) s += __shfl_xor_sync(0xffu, s, o);
        if (!tid) red[0] = s;
    }
    __syncthreads();
    float inv = rsqrtf(red[0] * (1.0f / H_DIM) + EPS);
    for (int i = tid; i < H_DIM; i += 256) {
        float v = xr[i] * inv * scale[i];
        sh[i] = v;
        g_tnorm_h[(size_t)t * H_DIM + i] = __float2bfloat16_rn(v);
    }
    __syncthreads();
    for (int e = warp; e < NE; e += 8) {
        const float* w = gw + (size_t)e * H_DIM;
        float s = 0.f;
        for (int i = lane; i < H_DIM; i += 32) s += sh[i] * w[i];
        for (int o = 16; o; o >>= 1) s += __shfl_xor_sync(~0u, s, o);
        if (!lane) logits[e] = s + gb[e];
    }
    __syncthreads();
    if (tid == 0) {
        unsigned used = 0;
        float v[TOPK]; int ix[TOPK];
        for (int k = 0; k < TOPK; k++) {
            float best = -3.4e38f; int bi = 0;
            for (int e2 = 0; e2 < NE; e2++)
                if (!((used >> e2) & 1u) && logits[e2] > best) { best = logits[e2]; bi = e2; }
            used |= 1u << bi; v[k] = best; ix[k] = bi;
        }
        float mx = v[0], sum = 0.f, w4[TOPK];
        for (int k = 0; k < TOPK; k++) { w4[k] = __expf(v[k] - mx); sum += w4[k]; }
        float rs = 1.f / sum;
        for (int k = 0; k < TOPK; k++) {
            g_expert_ids[t * TOPK + k] = ix[k];
            g_weights[t * TOPK + k] = w4[k] * rs;
            atomicAdd(&g_counts[ix[k]], 1);
        }
    }
}

// ------------------- kernel 2: deterministic scatter --------------------------
__global__ void k_scatter() {
    int e = threadIdx.x >> 5;
    int lane = threadIdx.x & 31;
    int base = 0;
    for (int i = 0; i < e; i++) base += g_counts[i];
    if (!lane) g_bases[e] = base;
    int running = 0;
    for (int j0 = 0; j0 < T_TOK * TOPK; j0 += 32) {
        int j = j0 + lane;
        int ee = g_expert_ids[j];
        unsigned m = __ballot_sync(~0u, ee == e);
        if (ee == e) {
            int slot = base + running + __popc(m & ((1u << lane) - 1u));
            g_slot_token[slot] = j >> 2;
            g_slot_weight[slot] = g_weights[j];
            g_token_slot[j] = slot;
        }
        running += __popc(m);
    }
}

// ------------------- kernel 3/4: bf16 HMMA GEMM, B direct-from-gmem -----------
// IS_G1=1: act_h[slot,f] = bf16(w_slot * swiglu(tnorm_h[token] @ w1[e]^T + b1[e]))
// IS_G1=0: y[slot,h]     = act_h[slot,:] @ w2[e]^T
template <int IS_G1>
__global__ __launch_bounds__(256, 2) void k_gemm(const float* __restrict__ W,
                                                 const float* __restrict__ bias) {
    const int Kd = 1024;
    const int Nd = IS_G1 ? TWO_F : H_DIM;
    const int e = blockIdx.z;
    const int cnt = g_counts[e];
    const int m0 = blockIdx.y * BM;
    if (m0 >= cnt) return;
    const int base = g_bases[e];
    const int n0 = blockIdx.x * BN;

    __shared__ __align__(16) __nv_bfloat16 As[2][STG_E];

    const int tid = threadIdx.x;
    const int warp = tid >> 5, lane = tid & 31;
    const int g = lane >> 2, tg = lane & 3;
    const int wm = (warp & 1) * 64;
    const int wn = (warp >> 1) * 32;

    // ---- A loader mapping: 512 16B chunks, 2 per thread ----
    const __nv_bfloat16* asrc[2]; uint32_t asz[2], aDst[2];
#pragma unroll
    for (int j = 0; j < 2; j++) {
        int c = tid + 256 * j;
        int row = c >> 2, u = c & 3;
        if (m0 + row < cnt) {
            int s = base + m0 + row;
            asrc[j] = (IS_G1 ? (g_tnorm_h + (size_t)g_slot_token[s] * H_DIM)
                             : (g_act_h + (size_t)s * F_DIM)) + u * 8;
            asz[j] = 16;
        } else {
            asrc[j] = g_tnorm_h; asz[j] = 0;
        }
        aDst[j] = (uint32_t)__cvta_generic_to_shared(As)
                  + (uint32_t)(row * 80 + u * 16);
    }

    // ---- B fragment pointers: col-blocks wn+ni*8, row g, k base 2tg ----
    const float* Wb = W + (size_t)e * Nd * Kd;
    const float* bp0 = Wb + (size_t)(n0 + wn + 0 + g) * Kd + 2 * tg;
    const float* bp1 = Wb + (size_t)(n0 + wn + 8 + g) * Kd + 2 * tg;
    const float* bp2 = Wb + (size_t)(n0 + wn + 16 + g) * Kd + 2 * tg;
    const float* bp3 = Wb + (size_t)(n0 + wn + 24 + g) * Kd + 2 * tg;

    // ---- ldmatrix per-lane A fragment base (stage 0) ----
    const int q = lane >> 3, qr = lane & 7;
    const uint32_t aFrag = (uint32_t)__cvta_generic_to_shared(As)
        + (uint32_t)((wm + (q & 1) * 8 + qr) * 80 + (q >> 1) * 16);

    float acc[4][4][4];
#pragma unroll
    for (int mi = 0; mi < 4; mi++)
#pragma unroll
        for (int ni = 0; ni < 4; ni++)
#pragma unroll
            for (int z = 0; z < 4; z++) acc[mi][ni][z] = 0.f;

    // ---- prologue: A stage0 via cp.async; B step0 frags ----
#pragma unroll
    for (int j = 0; j < 2; j++) cp16(aDst[j], asrc[j], asz[j]);
    cp_commit();
    uint32_t Bcur[8], Bnxt[8];
    ldB(bp0, bp1, bp2, bp3, 0, Bcur);

    const int NIT = Kd / BK;  // 32
#pragma unroll 1
    for (int it = 0; it < NIT; it++) {
        const uint32_t s = (uint32_t)(it & 1);
        cp_wait0();          // A stage s complete
        __syncthreads();     // all threads past iter it-1 reads; s^1 free
        if (it + 1 < NIT) {  // prefetch next A stage (overlapped with MMAs)
            const int k1 = (it + 1) * BK;
#pragma unroll
            for (int j = 0; j < 2; j++) cp16(aDst[j] + (s ^ 1) * STG_B, asrc[j] + k1, asz[j]);
            cp_commit();
        }
        const uint32_t aS = aFrag + s * STG_B;

        // ---- kk = 0: prefetch B(kk=1), compute with Bcur ----
        ldB(bp0, bp1, bp2, bp3, 16, Bnxt);
        {
            uint32_t a[4][4];
#pragma unroll
            for (int mi = 0; mi < 4; mi++)
                ldsm4(a[mi], aS + (uint32_t)(mi * 16 * 80));
#pragma unroll
            for (int mi = 0; mi < 4; mi++)
#pragma unroll
                for (int ni = 0; ni < 4; ni++)
                    mma_bf16(acc[mi][ni], a[mi], Bcur[2 * ni], Bcur[2 * ni + 1]);
        }
        // ---- kk = 1: prefetch next-iter B(kk=0), compute with Bnxt ----
        if (it + 1 < NIT) ldB(bp0, bp1, bp2, bp3, 32, Bcur);
        {
            uint32_t a[4][4];
#pragma unroll
            for (int mi = 0; mi < 4; mi++)
                ldsm4(a[mi], aS + (uint32_t)(mi * 16 * 80 + 32));
#pragma unroll
            for (int mi = 0; mi < 4; mi++)
#pragma unroll
                for (int ni = 0; ni < 4; ni++)
                    mma_bf16(acc[mi][ni], a[mi], Bnxt[2 * ni], Bnxt[2 * ni + 1]);
        }
        bp0 += BK; bp1 += BK; bp2 += BK; bp3 += BK;
    }

    // ---- epilogue (identical to R12) ----
#pragma unroll
    for (int mi = 0; mi < 4; mi++) {
#pragma unroll
        for (int h2 = 0; h2 < 2; h2++) {
            int r = m0 + wm + mi * 16 + g + h2 * 8;
            if (r >= cnt) continue;
            int slot = base + r;
            float wsl = IS_G1 ? g_slot_weight[slot] : 0.f;
#pragma unroll
            for (int ni = 0; ni < 4; ni++) {
                int ceven = n0 + wn + ni * 8 + 2 * tg;
                float v0 = acc[mi][ni][h2 * 2 + 0];
                float v1 = acc[mi][ni][h2 * 2 + 1];
                if (IS_G1) {
                    const float2 bb = *(const float2*)(bias + (size_t)e * TWO_F + ceven);
                    float glu = fminf(v0 + bb.x, LIMIT);
                    float lin = fminf(fmaxf(v1 + bb.y, -LIMIT), LIMIT);
                    float act = glu * (1.f / (1.f + __expf(-ALPHA * glu))) * (lin + 1.f);
                    g_act_h[(size_t)slot * F_DIM + (ceven >> 1)] =
                        __float2bfloat16_rn(wsl * act);
                } else {
                    *(float2*)(g_y + (size_t)slot * H_DIM + ceven) = make_float2(v0, v1);
                }
            }
        }
    }
}

// ------------------- kernel 5: combine + residual + b2 -------------------
__global__ void k_combine(const float* __restrict__ x, const float* __restrict__ b2,
                          float* __restrict__ out) {
    int t = blockIdx.x, tid = threadIdx.x;
    int s0 = g_token_slot[t * 4 + 0], s1 = g_token_slot[t * 4 + 1];
    int s2 = g_token_slot[t * 4 + 2], s3 = g_token_slot[t * 4 + 3];
    int e0 = g_expert_ids[t * 4 + 0], e1 = g_expert_ids[t * 4 + 1];
    int e2 = g_expert_ids[t * 4 + 2], e3 = g_expert_ids[t * 4 + 3];
    float w0 = g_weights[t * 4 + 0], w1v = g_weights[t * 4 + 1];
    float w2v = g_weights[t * 4 + 2], w3 = g_weights[t * 4 + 3];
    for (int i = tid; i < H_DIM; i += 256) {
        float v = x[(size_t)t * H_DIM + i];
        v += g_y[(size_t)s0 * H_DIM + i] + w0 * b2[(size_t)e0 * H_DIM + i];
        v += g_y[(size_t)s1 * H_DIM + i] + w1v * b2[(size_t)e1 * H_DIM + i];
        v += g_y[(size_t)s2 * H_DIM + i] + w2v * b2[(size_t)e2 * H_DIM + i];
        v += g_y[(size_t)s3 * H_DIM + i] + w3 * b2[(size_t)e3 * H_DIM + i];
        out[(size_t)t * H_DIM + i] = v;
    }
}

// ------------------- launcher -------------------
extern "C" void kernel_launch(void* const* d_in, const int* in_sizes, int n_in,
                              void* d_out, int out_size) {
    const float* x = (const float*)d_in[0];
    const float* norm_scale = (const float*)d_in[1];
    const float* gate_w = (const float*)d_in[2];
    const float* gate_b = (const float*)d_in[3];
    const float* w1 = (const float*)d_in[4];
    const float* b1 = (const float*)d_in[5];
    const float* w2 = (const float*)d_in[6];
    const float* b2 = (const float*)d_in[7];
    float* out = (float*)d_out;

    k_zero<<<1, 32>>>();
    k_gate<<<T_TOK, 256>>>(x, norm_scale, gate_w, gate_b);
    k_scatter<<<1, 1024>>>();
    dim3 grid1(TWO_F / BN, T_TOK / BM, NE); // (16, 8, 32)
    k_gemm<1><<<grid1, 256>>>(w1, b1);
    dim3 grid2(H_DIM / BN, T_TOK / BM, NE); // (8, 8, 32)
    k_gemm<0><<<grid2, 256>>>(w2, nullptr);
    k_combine<<<T_TOK, 256>>>(x, b2, out);
}